// round 13
// baseline (speedup 1.0000x reference)
#include <cuda_runtime.h>
#include <cuda_fp16.h>
#include <cstdint>

// Grouped MoE SwiGLU MLP via single-pass fp16 mma.sync (plain sm_103 target).
//   h  = silu(x @ w1[e]^T) * (x @ w3[e]^T)   [T, H]
//   out = h @ w2[e]^T                         [T, D]
// Phases A and B fused into one kernel; B row-tiles spin on per-tile counters.

#define E_CONST 8
#define D_CONST 1024
#define H_CONST 2816
#define T_MAX   16384
#define BM 128
#define MAX_TILES ((T_MAX / BM) + E_CONST)   // 136

#define KC  64        // K elems per smem chunk (64 fp16 = 128B rows)
#define STG 3         // pipeline stages

#define PA_NT (H_CONST / 64)      // 44 phase-A n-tiles
#define PB_NT (D_CONST / 128)     // 8  phase-B n-tiles
#define NA (PA_NT * MAX_TILES)    // 5984
#define NB (PB_NT * MAX_TILES)    // 1088

struct TileInfo { int row_start; int row_end; int expert; };
__device__ TileInfo g_tiles[MAX_TILES];
__device__ unsigned g_sync[MAX_TILES];

__device__ __half g_x [(size_t)T_MAX * D_CONST];
__device__ __half g_w1[(size_t)E_CONST * H_CONST * D_CONST];
__device__ __half g_w3[(size_t)E_CONST * H_CONST * D_CONST];
__device__ __half g_w2[(size_t)E_CONST * D_CONST * H_CONST];
__device__ __half g_h [(size_t)T_MAX * H_CONST];

// ------------------------------------------------------------------ helpers
__device__ __forceinline__ uint32_t smem_u32(const void* p) {
    uint32_t a;
    asm("{ .reg .u64 t; cvta.to.shared.u64 t, %1; cvt.u32.u64 %0, t; }" : "=r"(a) : "l"(p));
    return a;
}
__device__ __forceinline__ void cp16(uint32_t dst, const void* src, uint32_t sz) {
    asm volatile("cp.async.cg.shared.global [%0], [%1], 16, %2;"
                 :: "r"(dst), "l"(src), "r"(sz) : "memory");
}
#define CP_COMMIT() asm volatile("cp.async.commit_group;" ::: "memory")
#define CP_WAIT1()  asm volatile("cp.async.wait_group 1;" ::: "memory")

__device__ __forceinline__ void ldm4(uint32_t a, uint32_t& r0, uint32_t& r1,
                                     uint32_t& r2, uint32_t& r3) {
    asm volatile("ldmatrix.sync.aligned.m8n8.x4.shared.b16 {%0,%1,%2,%3}, [%4];"
                 : "=r"(r0), "=r"(r1), "=r"(r2), "=r"(r3) : "r"(a));
}
__device__ __forceinline__ void mma_acc(float c[4], const uint32_t a[4], const uint32_t b[2]) {
    asm volatile("mma.sync.aligned.m16n8k16.row.col.f32.f16.f16.f32 "
                 "{%0,%1,%2,%3}, {%4,%5,%6,%7}, {%8,%9}, {%0,%1,%2,%3};"
                 : "+f"(c[0]), "+f"(c[1]), "+f"(c[2]), "+f"(c[3])
                 : "r"(a[0]), "r"(a[1]), "r"(a[2]), "r"(a[3]), "r"(b[0]), "r"(b[1]));
}

// ------------------------------------------------------------------ setup / zero / convert
__global__ void setup_tiles_kernel(const int* __restrict__ counts) {
    if (threadIdx.x != 0 || blockIdx.x != 0) return;
    int off = 0, t = 0;
    for (int e = 0; e < E_CONST; ++e) {
        int c = counts[e];
        for (int s = 0; s < c && t < MAX_TILES; s += BM) {
            g_tiles[t].row_start = off + s;
            g_tiles[t].row_end   = off + (s + BM < c ? s + BM : c);
            g_tiles[t].expert    = e;
            ++t;
        }
        off += c;
    }
    for (; t < MAX_TILES; ++t) { g_tiles[t].row_start = 0; g_tiles[t].row_end = 0; g_tiles[t].expert = -1; }
    for (int i = 0; i < MAX_TILES; ++i) g_sync[i] = 0u;   // reset per launch (graph replay)
}

// zero only padding rows; total computed inline from counts (no setup dependency)
__global__ void zero_pad_kernel(float4* __restrict__ out, const int* __restrict__ counts) {
    int total = 0;
    #pragma unroll
    for (int e = 0; e < E_CONST; ++e) total += counts[e];
    int i = blockIdx.x * blockDim.x + threadIdx.x;     // one float4 per thread
    int row = i >> 8;                                  // D_CONST/4 = 256 float4 per row
    if (row >= T_MAX) return;
    if (row >= total) out[i] = make_float4(0.f, 0.f, 0.f, 0.f);
}

// 8 floats per thread: two float4 loads -> one uint4 (16B) store
__global__ void cvt_kernel(const float4* __restrict__ src, uint4* __restrict__ dst, int n8) {
    int i = blockIdx.x * blockDim.x + threadIdx.x;
    if (i >= n8) return;
    float4 v0 = src[i * 2];
    float4 v1 = src[i * 2 + 1];
    __half2 a = __floats2half2_rn(v0.x, v0.y);
    __half2 b = __floats2half2_rn(v0.z, v0.w);
    __half2 c = __floats2half2_rn(v1.x, v1.y);
    __half2 d = __floats2half2_rn(v1.z, v1.w);
    dst[i] = make_uint4(*(uint32_t*)&a, *(uint32_t*)&b, *(uint32_t*)&c, *(uint32_t*)&d);
}

// ------------------------------------------------------------------ fused phases
#define PA_A_TILE 16384                       // 128 rows x 128B
#define PA_B_TILE 8192                        // 64 rows x 128B
#define PA_STAGE  (PA_A_TILE + 2*PA_B_TILE)   // 32 KB
#define PA_NC     (D_CONST / KC)              // 16
#define PB_TILE   16384                       // 128 rows x 128B
#define PB_STAGE  (2 * PB_TILE)               // 32 KB
#define PB_NC     (H_CONST / KC)              // 44
#define FU_SMEM   (STG * PA_STAGE)            // 96 KB (== STG*PB_STAGE)

__global__ __launch_bounds__(256, 2) void fused_kernel(float* __restrict__ out) {
    extern __shared__ char smem[];
    const int tid = threadIdx.x, lane = tid & 31, wid = tid >> 5;
    const uint32_t sbase = smem_u32(smem);
    const int lq = tid & 7;
    const int lr0 = tid >> 3;

    const int arow = lane & 15;
    const int akhi = (lane >> 4) << 4;
    const int brl  = lane & 7;
    const int bg   = lane >> 3;
    const int bkb  = (bg & 1) << 4;
    const int bno  = (bg >> 1) << 3;
    const int l4 = lane >> 2, l2 = (lane & 3) * 2;

    if (blockIdx.x < NA) {
        // ======================= PHASE A CTA =======================
        const int t  = blockIdx.x / PA_NT;
        const int nx = blockIdx.x % PA_NT;
        TileInfo tile = g_tiles[t];
        if (tile.expert < 0) return;
        const int row0 = tile.row_start;
        const int rows_valid = tile.row_end - row0;
        const int n0 = nx * 64;
        const int wm = wid >> 1, wn = wid & 1;

        const size_t we = (size_t)tile.expert * H_CONST * D_CONST;
        const __half* __restrict__ A  = g_x  + (size_t)row0 * D_CONST;
        const __half* __restrict__ B1 = g_w1 + we + (size_t)n0 * D_CONST;
        const __half* __restrict__ B3 = g_w3 + we + (size_t)n0 * D_CONST;

        auto load_stage = [&](int s, int c) {
            const uint32_t st = sbase + s * PA_STAGE;
            const int k0 = c * KC;
            #pragma unroll
            for (int j = 0; j < 4; ++j) {               // A: 128 rows
                int r = lr0 + j * 32;
                uint32_t sz = (r < rows_valid) ? 16u : 0u;
                int rs = (r < rows_valid) ? r : 0;
                uint32_t d = st + r * 128 + ((lq * 16) ^ ((r & 7) << 4));
                cp16(d, A + (size_t)rs * D_CONST + k0 + lq * 8, sz);
            }
            #pragma unroll
            for (int j = 0; j < 2; ++j) {               // B1, B3: 64 rows each
                int r = lr0 + j * 32;
                uint32_t d = st + PA_A_TILE + r * 128 + ((lq * 16) ^ ((r & 7) << 4));
                const size_t go = (size_t)r * D_CONST + k0 + lq * 8;
                cp16(d,             B1 + go, 16);
                cp16(d + PA_B_TILE, B3 + go, 16);
            }
        };

        float acc1[2][4][4] = {};
        float acc3[2][4][4] = {};

        auto load_frag = [&](uint32_t st, int ks, uint32_t (&a)[2][4],
                             uint32_t (&b1)[4][2], uint32_t (&b3)[4][2]) {
            const int kb = ks * 32;
            #pragma unroll
            for (int mt = 0; mt < 2; ++mt) {
                int r = wm * 32 + mt * 16 + arow;
                uint32_t ad = st + r * 128 + ((kb + akhi) ^ ((r & 7) << 4));
                ldm4(ad, a[mt][0], a[mt][1], a[mt][2], a[mt][3]);
            }
            #pragma unroll
            for (int p = 0; p < 2; ++p) {
                int nr = wn * 32 + p * 16 + bno + brl;
                uint32_t swz = ((kb + bkb) ^ ((nr & 7) << 4));
                uint32_t bb1 = st + PA_A_TILE + nr * 128 + swz;
                ldm4(bb1,             b1[2*p][0], b1[2*p][1], b1[2*p+1][0], b1[2*p+1][1]);
                ldm4(bb1 + PA_B_TILE, b3[2*p][0], b3[2*p][1], b3[2*p+1][0], b3[2*p+1][1]);
            }
        };

        load_stage(0, 0); CP_COMMIT();
        load_stage(1, 1); CP_COMMIT();

        uint32_t af[2][2][4], b1f[2][4][2], b3f[2][4][2];

        for (int c = 0; c < PA_NC; ++c) {
            CP_WAIT1();
            __syncthreads();
            if (c + 2 < PA_NC) load_stage((c + 2) % STG, c + 2);
            CP_COMMIT();

            const uint32_t st = sbase + (c % STG) * PA_STAGE;
            load_frag(st, 0, af[0], b1f[0], b3f[0]);
            #pragma unroll
            for (int ks = 0; ks < 4; ++ks) {
                if (ks < 3) load_frag(st, ks + 1, af[(ks + 1) & 1], b1f[(ks + 1) & 1], b3f[(ks + 1) & 1]);
                #pragma unroll
                for (int mt = 0; mt < 2; ++mt)
                    #pragma unroll
                    for (int nt = 0; nt < 4; ++nt) {
                        mma_acc(acc1[mt][nt], af[ks & 1][mt], b1f[ks & 1][nt]);
                        mma_acc(acc3[mt][nt], af[ks & 1][mt], b3f[ks & 1][nt]);
                    }
            }
        }

        // epilogue: SwiGLU in registers, store h fp16
        #pragma unroll
        for (int mt = 0; mt < 2; ++mt)
            #pragma unroll
            for (int nt = 0; nt < 4; ++nt) {
                const int cidx = wn * 32 + nt * 8 + l2;
                #pragma unroll
                for (int half = 0; half < 2; ++half) {
                    int r = wm * 32 + mt * 16 + l4 + half * 8;
                    if (r < rows_valid) {
                        float z0 = acc1[mt][nt][half * 2 + 0];
                        float z1 = acc1[mt][nt][half * 2 + 1];
                        float v0 = (z0 / (1.f + __expf(-z0))) * acc3[mt][nt][half * 2 + 0];
                        float v1 = (z1 / (1.f + __expf(-z1))) * acc3[mt][nt][half * 2 + 1];
                        __half2 hv = __floats2half2_rn(v0, v1);
                        *(__half2*)(g_h + (size_t)(row0 + r) * H_CONST + n0 + cidx) = hv;
                    }
                }
            }

        // signal completion of this (tile, n-slice)
        __threadfence();
        __syncthreads();
        if (tid == 0) atomicAdd(&g_sync[t], 1u);

    } else {
        // ======================= PHASE B CTA =======================
        const int bx = blockIdx.x - NA;
        const int t  = bx / PB_NT;
        const int nx = bx % PB_NT;
        TileInfo tile = g_tiles[t];
        if (tile.expert < 0) return;
        const int row0 = tile.row_start;
        const int rows_valid = tile.row_end - row0;
        const int n0 = nx * 128;
        const int wm = wid >> 1, wn = wid & 1;

        // wait for all PA_NT n-slices of this row tile
        if (tid == 0) {
            for (;;) {
                unsigned v;
                asm volatile("ld.global.acquire.gpu.b32 %0, [%1];" : "=r"(v) : "l"(&g_sync[t]) : "memory");
                if (v >= (unsigned)PA_NT) break;
                __nanosleep(128);
            }
        }
        __syncthreads();
        __threadfence();

        const size_t we = (size_t)tile.expert * D_CONST * H_CONST;
        const __half* __restrict__ A = g_h  + (size_t)row0 * H_CONST;
        const __half* __restrict__ B = g_w2 + we + (size_t)n0 * H_CONST;

        auto load_stage = [&](int s, int c) {
            const uint32_t st = sbase + s * PB_STAGE;
            const int k0 = c * KC;
            #pragma unroll
            for (int j = 0; j < 4; ++j) {
                int r = lr0 + j * 32;
                uint32_t sz = (r < rows_valid) ? 16u : 0u;
                int rs = (r < rows_valid) ? r : 0;
                uint32_t swo = r * 128 + ((lq * 16) ^ ((r & 7) << 4));
                cp16(st + swo,           A + (size_t)rs * H_CONST + k0 + lq * 8, sz);
                cp16(st + PB_TILE + swo, B + (size_t)r  * H_CONST + k0 + lq * 8, 16);
            }
        };

        float acc[2][8][4] = {};

        auto load_frag = [&](uint32_t st, int ks, uint32_t (&a)[2][4], uint32_t (&b)[8][2]) {
            const int kb = ks * 32;
            #pragma unroll
            for (int mt = 0; mt < 2; ++mt) {
                int r = wm * 32 + mt * 16 + arow;
                uint32_t ad = st + r * 128 + ((kb + akhi) ^ ((r & 7) << 4));
                ldm4(ad, a[mt][0], a[mt][1], a[mt][2], a[mt][3]);
            }
            #pragma unroll
            for (int p = 0; p < 4; ++p) {
                int nr = wn * 64 + p * 16 + bno + brl;
                uint32_t bb = st + PB_TILE + nr * 128 + ((kb + bkb) ^ ((nr & 7) << 4));
                ldm4(bb, b[2*p][0], b[2*p][1], b[2*p+1][0], b[2*p+1][1]);
            }
        };

        load_stage(0, 0); CP_COMMIT();
        load_stage(1, 1); CP_COMMIT();

        uint32_t af[2][2][4], bf[2][8][2];

        for (int c = 0; c < PB_NC; ++c) {
            CP_WAIT1();
            __syncthreads();
            if (c + 2 < PB_NC) load_stage((c + 2) % STG, c + 2);
            CP_COMMIT();

            const uint32_t st = sbase + (c % STG) * PB_STAGE;
            load_frag(st, 0, af[0], bf[0]);
            #pragma unroll
            for (int ks = 0; ks < 4; ++ks) {
                if (ks < 3) load_frag(st, ks + 1, af[(ks + 1) & 1], bf[(ks + 1) & 1]);
                #pragma unroll
                for (int mt = 0; mt < 2; ++mt)
                    #pragma unroll
                    for (int nt = 0; nt < 8; ++nt)
                        mma_acc(acc[mt][nt], af[ks & 1][mt], bf[ks & 1][nt]);
            }
        }

        #pragma unroll
        for (int mt = 0; mt < 2; ++mt)
            #pragma unroll
            for (int nt = 0; nt < 8; ++nt) {
                const int col = n0 + wn * 64 + nt * 8 + l2;
                #pragma unroll
                for (int half = 0; half < 2; ++half) {
                    int rl = wm * 32 + mt * 16 + l4 + half * 8;
                    if (rl < rows_valid) {
                        float2 v;
                        v.x = acc[mt][nt][half * 2 + 0];
                        v.y = acc[mt][nt][half * 2 + 1];
                        *(float2*)(out + (size_t)(row0 + rl) * D_CONST + col) = v;
                    }
                }
            }
    }
}

// ------------------------------------------------------------------ launcher
extern "C" void kernel_launch(void* const* d_in, const int* in_sizes, int n_in,
                              void* d_out, int out_size) {
    const float* x      = (const float*)d_in[0];
    const float* w1     = (const float*)d_in[1];
    const float* w2     = (const float*)d_in[2];
    const float* w3     = (const float*)d_in[3];
    const int*   counts = (const int*)  d_in[4];
    float* out = (float*)d_out;

    cudaFuncSetAttribute(fused_kernel, cudaFuncAttributeMaxDynamicSharedMemorySize, FU_SMEM);

    setup_tiles_kernel<<<1, 32>>>(counts);

    const int n4 = out_size / 4;
    zero_pad_kernel<<<(n4 + 255) / 256, 256>>>((float4*)out, counts);

    {
        __half *xp, *w1p, *w2p, *w3p;
        cudaGetSymbolAddress((void**)&xp,  g_x);
        cudaGetSymbolAddress((void**)&w1p, g_w1);
        cudaGetSymbolAddress((void**)&w2p, g_w2);
        cudaGetSymbolAddress((void**)&w3p, g_w3);

        int nx8 = (T_MAX * D_CONST) / 8;
        cvt_kernel<<<(nx8 + 255) / 256, 256>>>((const float4*)x, (uint4*)xp, nx8);
        int nw8 = (E_CONST * H_CONST * D_CONST) / 8;
        cvt_kernel<<<(nw8 + 255) / 256, 256>>>((const float4*)w1, (uint4*)w1p, nw8);
        cvt_kernel<<<(nw8 + 255) / 256, 256>>>((const float4*)w3, (uint4*)w3p, nw8);
        cvt_kernel<<<(nw8 + 255) / 256, 256>>>((const float4*)w2, (uint4*)w2p, nw8);
    }

    fused_kernel<<<NA + NB, 256, FU_SMEM>>>(out);
}

// round 15
// speedup vs baseline: 1.0271x; 1.0271x over previous
#include <cuda_runtime.h>
#include <cuda_fp16.h>
#include <cstdint>

// Grouped MoE SwiGLU MLP via single-pass fp16 mma.sync (plain sm_103 target).
//   h  = silu(x @ w1[e]^T) * (x @ w3[e]^T)   [T, H]
//   out = h @ w2[e]^T                         [T, D]

#define E_CONST 8
#define D_CONST 1024
#define H_CONST 2816
#define T_MAX   16384
#define BM 128
#define MAX_TILES ((T_MAX / BM) + E_CONST)   // 136

#define KC  64        // K elems per smem chunk (64 fp16 = 128B rows)
#define STG 3         // pipeline stages

struct TileInfo { int row_start; int row_end; int expert; };
__device__ TileInfo g_tiles[MAX_TILES];

__device__ __half g_x [(size_t)T_MAX * D_CONST];
__device__ __half g_w1[(size_t)E_CONST * H_CONST * D_CONST];
__device__ __half g_w3[(size_t)E_CONST * H_CONST * D_CONST];
__device__ __half g_w2[(size_t)E_CONST * D_CONST * H_CONST];
__device__ __half g_h [(size_t)T_MAX * H_CONST];

// ------------------------------------------------------------------ helpers
__device__ __forceinline__ uint32_t smem_u32(const void* p) {
    uint32_t a;
    asm("{ .reg .u64 t; cvta.to.shared.u64 t, %1; cvt.u32.u64 %0, t; }" : "=r"(a) : "l"(p));
    return a;
}
__device__ __forceinline__ void cp16(uint32_t dst, const void* src, uint32_t sz) {
    asm volatile("cp.async.cg.shared.global [%0], [%1], 16, %2;"
                 :: "r"(dst), "l"(src), "r"(sz) : "memory");
}
#define CP_COMMIT() asm volatile("cp.async.commit_group;" ::: "memory")
#define CP_WAIT1()  asm volatile("cp.async.wait_group 1;" ::: "memory")

__device__ __forceinline__ void ldm4(uint32_t a, uint32_t& r0, uint32_t& r1,
                                     uint32_t& r2, uint32_t& r3) {
    asm volatile("ldmatrix.sync.aligned.m8n8.x4.shared.b16 {%0,%1,%2,%3}, [%4];"
                 : "=r"(r0), "=r"(r1), "=r"(r2), "=r"(r3) : "r"(a));
}
__device__ __forceinline__ void mma_acc(float c[4], const uint32_t a[4], const uint32_t b[2]) {
    asm volatile("mma.sync.aligned.m16n8k16.row.col.f32.f16.f16.f32 "
                 "{%0,%1,%2,%3}, {%4,%5,%6,%7}, {%8,%9}, {%0,%1,%2,%3};"
                 : "+f"(c[0]), "+f"(c[1]), "+f"(c[2]), "+f"(c[3])
                 : "r"(a[0]), "r"(a[1]), "r"(a[2]), "r"(a[3]), "r"(b[0]), "r"(b[1]));
}

// ------------------------------------------------------------------ setup / zero / convert
__global__ void setup_tiles_kernel(const int* __restrict__ counts) {
    if (threadIdx.x != 0 || blockIdx.x != 0) return;
    int off = 0, t = 0;
    for (int e = 0; e < E_CONST; ++e) {
        int c = counts[e];
        for (int s = 0; s < c && t < MAX_TILES; s += BM) {
            g_tiles[t].row_start = off + s;
            g_tiles[t].row_end   = off + (s + BM < c ? s + BM : c);
            g_tiles[t].expert    = e;
            ++t;
        }
        off += c;
    }
    for (; t < MAX_TILES; ++t) { g_tiles[t].row_start = 0; g_tiles[t].row_end = 0; g_tiles[t].expert = -1; }
}

// zero only padding rows; total computed inline from counts (no setup dependency)
__global__ void zero_pad_kernel(float4* __restrict__ out, const int* __restrict__ counts) {
    int total = 0;
    #pragma unroll
    for (int e = 0; e < E_CONST; ++e) total += counts[e];
    int i = blockIdx.x * blockDim.x + threadIdx.x;     // one float4 per thread
    int row = i >> 8;                                  // D_CONST/4 = 256 float4 per row
    if (row >= T_MAX) return;
    if (row >= total) out[i] = make_float4(0.f, 0.f, 0.f, 0.f);
}

// Single segmented fp32->fp16 conversion over x, w1, w3, w2.
// 8 floats per thread: two float4 loads -> one uint4 (16B) store.
#define NX8 ((T_MAX * D_CONST) / 8)                    // 2,097,152
#define NW8 ((E_CONST * H_CONST * D_CONST) / 8)        // 2,883,584
#define NCVT (NX8 + 3 * NW8)                           // 10,747,904

__global__ void cvt_all_kernel(const float4* __restrict__ x,  const float4* __restrict__ w1,
                               const float4* __restrict__ w3, const float4* __restrict__ w2,
                               uint4* __restrict__ xd, uint4* __restrict__ w1d,
                               uint4* __restrict__ w3d, uint4* __restrict__ w2d) {
    long i = (long)blockIdx.x * blockDim.x + threadIdx.x;
    if (i >= NCVT) return;
    const float4* src; uint4* dst; long j;
    if (i < NX8)                { src = x;  dst = xd;  j = i; }
    else if (i < NX8 + NW8)     { src = w1; dst = w1d; j = i - NX8; }
    else if (i < NX8 + 2*NW8)   { src = w3; dst = w3d; j = i - NX8 - NW8; }
    else                        { src = w2; dst = w2d; j = i - NX8 - 2*NW8; }
    float4 v0 = src[j * 2];
    float4 v1 = src[j * 2 + 1];
    __half2 a = __floats2half2_rn(v0.x, v0.y);
    __half2 b = __floats2half2_rn(v0.z, v0.w);
    __half2 c = __floats2half2_rn(v1.x, v1.y);
    __half2 d = __floats2half2_rn(v1.z, v1.w);
    dst[j] = make_uint4(*(uint32_t*)&a, *(uint32_t*)&b, *(uint32_t*)&c, *(uint32_t*)&d);
}

// ------------------------------------------------------------------ phase A
// CTA tile 128x64, 256 threads, 2 CTAs/SM. Warp grid 4x2; EACH warp computes a
// 32x32 patch of BOTH S1=x@w1^T and S3=x@w3^T -> SwiGLU fused in registers.
// blockIdx.x = n-tile (L2 locality), blockIdx.y = row-tile.
#define PA_A_TILE 16384                       // 128 rows x 128B
#define PA_B_TILE 8192                        // 64 rows x 128B
#define PA_STAGE  (PA_A_TILE + 2*PA_B_TILE)   // 32 KB
#define PA_SMEM   (STG * PA_STAGE)            // 96 KB
#define PA_NC     (D_CONST / KC)              // 16

__global__ __launch_bounds__(256, 2) void phaseA_kernel() {
    extern __shared__ char smem[];
    TileInfo tile = g_tiles[blockIdx.y];
    if (tile.expert < 0) return;
    const int row0 = tile.row_start;
    const int rows_valid = tile.row_end - row0;
    const int n0 = blockIdx.x * 64;

    const int tid = threadIdx.x, lane = tid & 31, wid = tid >> 5;
    const int wm = wid >> 1, wn = wid & 1;   // 4 row groups x 2 col halves (32 cols)
    const uint32_t sbase = smem_u32(smem);

    const size_t we = (size_t)tile.expert * H_CONST * D_CONST;
    const __half* __restrict__ A  = g_x  + (size_t)row0 * D_CONST;
    const __half* __restrict__ B1 = g_w1 + we + (size_t)n0 * D_CONST;
    const __half* __restrict__ B3 = g_w3 + we + (size_t)n0 * D_CONST;

    const int lq = tid & 7;          // 16B chunk within 128B row
    const int lr0 = tid >> 3;        // base row (0..31)

    auto load_stage = [&](int s, int c) {
        const uint32_t st = sbase + s * PA_STAGE;
        const int k0 = c * KC;
        #pragma unroll
        for (int j = 0; j < 4; ++j) {               // A: 128 rows
            int r = lr0 + j * 32;
            uint32_t sz = (r < rows_valid) ? 16u : 0u;
            int rs = (r < rows_valid) ? r : 0;
            uint32_t d = st + r * 128 + ((lq * 16) ^ ((r & 7) << 4));
            cp16(d, A + (size_t)rs * D_CONST + k0 + lq * 8, sz);
        }
        #pragma unroll
        for (int j = 0; j < 2; ++j) {               // B1, B3: 64 rows each
            int r = lr0 + j * 32;
            uint32_t d = st + PA_A_TILE + r * 128 + ((lq * 16) ^ ((r & 7) << 4));
            const size_t go = (size_t)r * D_CONST + k0 + lq * 8;
            cp16(d,             B1 + go, 16);
            cp16(d + PA_B_TILE, B3 + go, 16);
        }
    };

    float acc1[2][4][4] = {};    // 32x32 of S1
    float acc3[2][4][4] = {};    // 32x32 of S3

    const int arow = lane & 15;
    const int akhi = (lane >> 4) << 4;        // 0 / 16 bytes
    const int brl  = lane & 7;
    const int bg   = lane >> 3;
    const int bkb  = (bg & 1) << 4;
    const int bno  = (bg >> 1) << 3;

    auto load_frag = [&](uint32_t st, int ks, uint32_t (&a)[2][4],
                         uint32_t (&b1)[4][2], uint32_t (&b3)[4][2]) {
        const int kb = ks * 32;
        #pragma unroll
        for (int mt = 0; mt < 2; ++mt) {
            int r = wm * 32 + mt * 16 + arow;
            uint32_t ad = st + r * 128 + ((kb + akhi) ^ ((r & 7) << 4));
            ldm4(ad, a[mt][0], a[mt][1], a[mt][2], a[mt][3]);
        }
        #pragma unroll
        for (int p = 0; p < 2; ++p) {
            int nr = wn * 32 + p * 16 + bno + brl;
            uint32_t swz = ((kb + bkb) ^ ((nr & 7) << 4));
            uint32_t bb1 = st + PA_A_TILE + nr * 128 + swz;
            ldm4(bb1,             b1[2*p][0], b1[2*p][1], b1[2*p+1][0], b1[2*p+1][1]);
            ldm4(bb1 + PA_B_TILE, b3[2*p][0], b3[2*p][1], b3[2*p+1][0], b3[2*p+1][1]);
        }
    };

    load_stage(0, 0); CP_COMMIT();
    load_stage(1, 1); CP_COMMIT();

    uint32_t af[2][2][4], b1f[2][4][2], b3f[2][4][2];

    for (int c = 0; c < PA_NC; ++c) {
        CP_WAIT1();
        __syncthreads();
        if (c + 2 < PA_NC) load_stage((c + 2) % STG, c + 2);
        CP_COMMIT();

        const uint32_t st = sbase + (c % STG) * PA_STAGE;
        load_frag(st, 0, af[0], b1f[0], b3f[0]);
        #pragma unroll
        for (int ks = 0; ks < 4; ++ks) {
            if (ks < 3) load_frag(st, ks + 1, af[(ks + 1) & 1], b1f[(ks + 1) & 1], b3f[(ks + 1) & 1]);
            #pragma unroll
            for (int mt = 0; mt < 2; ++mt)
                #pragma unroll
                for (int nt = 0; nt < 4; ++nt) {
                    mma_acc(acc1[mt][nt], af[ks & 1][mt], b1f[ks & 1][nt]);
                    mma_acc(acc3[mt][nt], af[ks & 1][mt], b3f[ks & 1][nt]);
                }
        }
    }

    // epilogue: SwiGLU entirely in registers, store h fp16 (no smem, no barriers)
    const int l4 = lane >> 2, l2 = (lane & 3) * 2;
    #pragma unroll
    for (int mt = 0; mt < 2; ++mt)
        #pragma unroll
        for (int nt = 0; nt < 4; ++nt) {
            const int cidx = wn * 32 + nt * 8 + l2;
            #pragma unroll
            for (int half = 0; half < 2; ++half) {
                int r = wm * 32 + mt * 16 + l4 + half * 8;
                if (r < rows_valid) {
                    float z0 = acc1[mt][nt][half * 2 + 0];
                    float z1 = acc1[mt][nt][half * 2 + 1];
                    float v0 = (z0 / (1.f + __expf(-z0))) * acc3[mt][nt][half * 2 + 0];
                    float v1 = (z1 / (1.f + __expf(-z1))) * acc3[mt][nt][half * 2 + 1];
                    __half2 hv = __floats2half2_rn(v0, v1);
                    *(__half2*)(g_h + (size_t)(row0 + r) * H_CONST + n0 + cidx) = hv;
                }
            }
        }
}

// ------------------------------------------------------------------ phase B
// CTA tile 128x128, 256 threads, 2 CTAs/SM: out = h @ w2^T. Warp tile 32x64.
// blockIdx.x = n-tile, blockIdx.y = row-tile.
#define PB_TILE  16384                        // 128 rows x 128B
#define PB_STAGE (2 * PB_TILE)                // 32 KB
#define PB_SMEM  (STG * PB_STAGE)             // 96 KB
#define PB_NC    (H_CONST / KC)               // 44

__global__ __launch_bounds__(256, 2) void phaseB_kernel(float* __restrict__ out) {
    extern __shared__ char smem[];
    TileInfo tile = g_tiles[blockIdx.y];
    if (tile.expert < 0) return;
    const int row0 = tile.row_start;
    const int rows_valid = tile.row_end - row0;
    const int n0 = blockIdx.x * 128;

    const int tid = threadIdx.x, lane = tid & 31, wid = tid >> 5;
    const int wm = wid >> 1, wn = wid & 1;
    const uint32_t sbase = smem_u32(smem);

    const size_t we = (size_t)tile.expert * D_CONST * H_CONST;
    const __half* __restrict__ A = g_h  + (size_t)row0 * H_CONST;
    const __half* __restrict__ B = g_w2 + we + (size_t)n0 * H_CONST;

    const int lq = tid & 7;
    const int lr0 = tid >> 3;

    auto load_stage = [&](int s, int c) {
        const uint32_t st = sbase + s * PB_STAGE;
        const int k0 = c * KC;
        #pragma unroll
        for (int j = 0; j < 4; ++j) {
            int r = lr0 + j * 32;
            uint32_t sz = (r < rows_valid) ? 16u : 0u;
            int rs = (r < rows_valid) ? r : 0;
            uint32_t swo = r * 128 + ((lq * 16) ^ ((r & 7) << 4));
            cp16(st + swo,           A + (size_t)rs * H_CONST + k0 + lq * 8, sz);
            cp16(st + PB_TILE + swo, B + (size_t)r  * H_CONST + k0 + lq * 8, 16);
        }
    };

    float acc[2][8][4] = {};

    const int arow = lane & 15;
    const int akhi = (lane >> 4) << 4;
    const int brl  = lane & 7;
    const int bg   = lane >> 3;
    const int bkb  = (bg & 1) << 4;
    const int bno  = (bg >> 1) << 3;

    auto load_frag = [&](uint32_t st, int ks, uint32_t (&a)[2][4], uint32_t (&b)[8][2]) {
        const int kb = ks * 32;
        #pragma unroll
        for (int mt = 0; mt < 2; ++mt) {
            int r = wm * 32 + mt * 16 + arow;
            uint32_t ad = st + r * 128 + ((kb + akhi) ^ ((r & 7) << 4));
            ldm4(ad, a[mt][0], a[mt][1], a[mt][2], a[mt][3]);
        }
        #pragma unroll
        for (int p = 0; p < 4; ++p) {
            int nr = wn * 64 + p * 16 + bno + brl;
            uint32_t bb = st + PB_TILE + nr * 128 + ((kb + bkb) ^ ((nr & 7) << 4));
            ldm4(bb, b[2*p][0], b[2*p][1], b[2*p+1][0], b[2*p+1][1]);
        }
    };

    load_stage(0, 0); CP_COMMIT();
    load_stage(1, 1); CP_COMMIT();

    uint32_t af[2][2][4], bf[2][8][2];

    for (int c = 0; c < PB_NC; ++c) {
        CP_WAIT1();
        __syncthreads();
        if (c + 2 < PB_NC) load_stage((c + 2) % STG, c + 2);
        CP_COMMIT();

        const uint32_t st = sbase + (c % STG) * PB_STAGE;
        load_frag(st, 0, af[0], bf[0]);
        #pragma unroll
        for (int ks = 0; ks < 4; ++ks) {
            if (ks < 3) load_frag(st, ks + 1, af[(ks + 1) & 1], bf[(ks + 1) & 1]);
            #pragma unroll
            for (int mt = 0; mt < 2; ++mt)
                #pragma unroll
                for (int nt = 0; nt < 8; ++nt)
                    mma_acc(acc[mt][nt], af[ks & 1][mt], bf[ks & 1][nt]);
        }
    }

    const int l4 = lane >> 2, l2 = (lane & 3) * 2;
    #pragma unroll
    for (int mt = 0; mt < 2; ++mt)
        #pragma unroll
        for (int nt = 0; nt < 8; ++nt) {
            const int col = n0 + wn * 64 + nt * 8 + l2;
            #pragma unroll
            for (int half = 0; half < 2; ++half) {
                int rl = wm * 32 + mt * 16 + l4 + half * 8;
                if (rl < rows_valid) {
                    float2 v;
                    v.x = acc[mt][nt][half * 2 + 0];
                    v.y = acc[mt][nt][half * 2 + 1];
                    *(float2*)(out + (size_t)(row0 + rl) * D_CONST + col) = v;
                }
            }
        }
}

// ------------------------------------------------------------------ launcher
extern "C" void kernel_launch(void* const* d_in, const int* in_sizes, int n_in,
                              void* d_out, int out_size) {
    const float* x      = (const float*)d_in[0];
    const float* w1     = (const float*)d_in[1];
    const float* w2     = (const float*)d_in[2];
    const float* w3     = (const float*)d_in[3];
    const int*   counts = (const int*)  d_in[4];
    float* out = (float*)d_out;

    cudaFuncSetAttribute(phaseA_kernel, cudaFuncAttributeMaxDynamicSharedMemorySize, PA_SMEM);
    cudaFuncSetAttribute(phaseB_kernel, cudaFuncAttributeMaxDynamicSharedMemorySize, PB_SMEM);

    setup_tiles_kernel<<<1, 32>>>(counts);

    const int n4 = out_size / 4;
    zero_pad_kernel<<<(n4 + 255) / 256, 256>>>((float4*)out, counts);

    {
        __half *xp, *w1p, *w2p, *w3p;
        cudaGetSymbolAddress((void**)&xp,  g_x);
        cudaGetSymbolAddress((void**)&w1p, g_w1);
        cudaGetSymbolAddress((void**)&w2p, g_w2);
        cudaGetSymbolAddress((void**)&w3p, g_w3);

        cvt_all_kernel<<<(NCVT + 255) / 256, 256>>>(
            (const float4*)x, (const float4*)w1, (const float4*)w3, (const float4*)w2,
            (uint4*)xp, (uint4*)w1p, (uint4*)w3p, (uint4*)w2p);
    }

    dim3 ga(H_CONST / 64, MAX_TILES);    // 44 x 136
    phaseA_kernel<<<ga, 256, PA_SMEM>>>();

    dim3 gb(D_CONST / 128, MAX_TILES);   // 8 x 136
    phaseB_kernel<<<gb, 256, PB_SMEM>>>(out);
}